// round 7
// baseline (speedup 1.0000x reference)
#include <cuda_runtime.h>

#define DD 4096
#define NSM 148
#define THREADS 1024          // 32 warps, one block per SM
#define NSTAT 24              // static rows per block; 148*24 = 3552
#define POOLBASE (NSM * NSTAT)
#define MATSZ ((size_t)DD * DD)

// ping-pong node buffers (scatter idx is a permutation -> fully overwritten each layer)
__device__ float g_buf0[DD];
__device__ float g_buf1[DD];
// per-layer work-stealing tickets + reset bookkeeping (zero at load; each launch leaves them zero)
__device__ unsigned g_tick[8];
__device__ unsigned g_done[8];

template<bool MASK, bool GATHER, bool SCATTER>
__global__ void __launch_bounds__(THREADS, 1)
gemv_layer(const float* __restrict__ W,
           const float* __restrict__ O,
           const float* __restrict__ bias,
           const float* __restrict__ src,
           const int*   __restrict__ gidx,
           const int*   __restrict__ sidx,
           float*       __restrict__ dst,
           int slot)
{
    __shared__ float s_in[DD];
    const int t    = threadIdx.x;
    const int lane = t & 31;
    const int w    = t >> 5;

    // ---------- gather input vector into smem (4 independent loads -> one L2 latency) ----------
    {
        float tmp[4];
        if (GATHER) {
            int gi[4];
            #pragma unroll
            for (int r = 0; r < 4; ++r) gi[r] = __ldg(gidx + t + r * THREADS);
            #pragma unroll
            for (int r = 0; r < 4; ++r) tmp[r] = __ldcg(src + gi[r]);   // L1 bypass: fresh data
        } else {
            #pragma unroll
            for (int r = 0; r < 4; ++r) tmp[r] = __ldg(src + t + r * THREADS);
        }
        #pragma unroll
        for (int r = 0; r < 4; ++r) s_in[t + r * THREADS] = tmp[r];
    }
    __syncthreads();

    const float4* __restrict__ s4 = reinterpret_cast<const float4*>(s_in) + lane;

    // ---------- row loop: 24 static rows per block, then steal from the global pool ----------
    int row;
    if (w < NSTAT) {
        row = blockIdx.x * NSTAT + w;
    } else {
        unsigned nr;
        if (lane == 0) nr = POOLBASE + atomicAdd(&g_tick[slot], 1u);
        row = (int)__shfl_sync(0xffffffffu, nr, 0);
    }

    while (row < DD) {
        // hoist epilogue loads off the critical path
        float bv = 0.f; int sc = 0;
        if (lane == 0) {
            bv = __ldg(bias + row);
            sc = SCATTER ? __ldg(sidx + row) : row;
        }

        const float4* __restrict__ w4 = reinterpret_cast<const float4*>(W + (size_t)row * DD) + lane;
        float acc0 = 0.f, acc1 = 0.f;

        if (MASK) {
            const float4* __restrict__ o4 = reinterpret_cast<const float4*>(O + (size_t)row * DD) + lane;
            float4 wb[4], ob[4];
            #pragma unroll
            for (int base = 0; base < 32; base += 4) {
                #pragma unroll
                for (int u = 0; u < 4; ++u) wb[u] = __ldcs(w4 + (base + u) * 32);
                #pragma unroll
                for (int u = 0; u < 4; ++u) ob[u] = __ldcs(o4 + (base + u) * 32);
                #pragma unroll
                for (int u = 0; u < 4; ++u) {
                    const float4 xi = s4[(base + u) * 32];
                    acc0 = fmaf(wb[u].x * ob[u].x, xi.x, acc0);
                    acc1 = fmaf(wb[u].y * ob[u].y, xi.y, acc1);
                    acc0 = fmaf(wb[u].z * ob[u].z, xi.z, acc0);
                    acc1 = fmaf(wb[u].w * ob[u].w, xi.w, acc1);
                }
            }
        } else {
            float4 wb[8];
            #pragma unroll
            for (int base = 0; base < 32; base += 8) {
                #pragma unroll
                for (int u = 0; u < 8; ++u) wb[u] = __ldcs(w4 + (base + u) * 32);
                #pragma unroll
                for (int u = 0; u < 8; ++u) {
                    const float4 xi = s4[(base + u) * 32];
                    acc0 = fmaf(wb[u].x, xi.x, acc0);
                    acc1 = fmaf(wb[u].y, xi.y, acc1);
                    acc0 = fmaf(wb[u].z, xi.z, acc0);
                    acc1 = fmaf(wb[u].w, xi.w, acc1);
                }
            }
        }

        float acc = acc0 + acc1;
        #pragma unroll
        for (int off = 16; off; off >>= 1) acc += __shfl_down_sync(0xffffffffu, acc, off);

        if (lane == 0) dst[sc] = fmaxf(acc + bv, 0.f);

        // steal next row
        unsigned nr;
        if (lane == 0) nr = POOLBASE + atomicAdd(&g_tick[slot], 1u);
        row = (int)__shfl_sync(0xffffffffu, nr, 0);
    }

    // ---------- replay-safe counter reset: last block to finish zeroes the slot ----------
    __syncthreads();
    if (t == 0) {
        unsigned d = atomicAdd(&g_done[slot], 1u);
        if (d == NSM - 1u) {
            *(volatile unsigned*)&g_tick[slot] = 0u;
            *(volatile unsigned*)&g_done[slot] = 0u;
        }
    }
}

extern "C" void kernel_launch(void* const* d_in, const int* in_sizes, int n_in,
                              void* d_out, int out_size)
{
    const float* x       = (const float*)d_in[0];   // [D]
    const float* W_in    = (const float*)d_in[1];   // [D, D]
    const float* b_in    = (const float*)d_in[2];   // [D]
    const float* weights = (const float*)d_in[3];   // [L, D, D]
    const float* orders  = (const float*)d_in[4];   // [L, D, D]
    const float* biases  = (const float*)d_in[5];   // [L, D]
    const int*   gidx    = (const int*)d_in[6];     // [L, D]
    const int*   sidx    = (const int*)d_in[7];     // [L+1, D]
    float*       out     = (float*)d_out;           // [D]

    float *b0 = nullptr, *b1 = nullptr;
    cudaGetSymbolAddress((void**)&b0, g_buf0);
    cudaGetSymbolAddress((void**)&b1, g_buf1);

    dim3 grid(NSM), blk(THREADS);

    // input layer: relu(W_in @ x + b_in), scattered via scatter_idx[0]
    gemv_layer<false, false, true><<<grid, blk>>>(
        W_in, nullptr, b_in, x, nullptr, sidx, b0, 0);

    // layer 0: gather g[0], masked GEMV, scatter s[1]
    gemv_layer<true, true, true><<<grid, blk>>>(
        weights, orders, biases, b0, gidx, sidx + DD, b1, 1);

    // layer 1
    gemv_layer<true, true, true><<<grid, blk>>>(
        weights + MATSZ, orders + MATSZ, biases + DD, b1, gidx + DD, sidx + 2 * DD, b0, 2);

    // layer 2
    gemv_layer<true, true, true><<<grid, blk>>>(
        weights + 2 * MATSZ, orders + 2 * MATSZ, biases + 2 * DD, b0, gidx + 2 * DD, sidx + 3 * DD, b1, 3);

    // layer 3: final layer — output is the PRE-scatter activation, straight to d_out
    gemv_layer<true, true, false><<<grid, blk>>>(
        weights + 3 * MATSZ, orders + 3 * MATSZ, biases + 3 * DD, b1, gidx + 3 * DD, nullptr, out, 4);
}